// round 14
// baseline (speedup 1.0000x reference)
#include <cuda_runtime.h>
#include <cuda_fp16.h>
#include <cstdint>

#define cN0 200000
#define cN1 50000
#define cN2 10000
#define cE0 1600000
#define cE1 320000
#define NB0 49
#define NB1 10

// ---------------- device scratch ----------------
__device__ __align__(128) __half g_xh[cN0 * 256];      // all x, fp16
__device__ __align__(128) __half g_hh[cN1 * 256];      // h (layer-0 out), fp16
__device__ __align__(128) __half g_mean0h[cN1 * 256];
__device__ __align__(128) __half g_mean1h[cN2 * 256];
__device__ __align__(128) __half g_attr0h[cN1 * 256];  // attr[batch0]
__device__ __align__(128) __half g_attr1h[cN2 * 256];  // attr[batch1]
__device__ __align__(128) __half g_Wh0[256 * 768];     // [n][k]
__device__ __align__(128) __half g_Wh1[128 * 768];
__device__ float g_bias0[256];
__device__ float g_bias1[128];
// zero at module load; re-zeroed by agg0 tail blocks each run (entry invariant)
__device__ __align__(16) int g_cnt0[cN1];
__device__ __align__(16) int g_cnt1[cN2];
__device__ int g_rp0[cN1 + 1];
__device__ int g_rp1[cN2 + 1];
__device__ __align__(16) int g_rank0[cE0];  // per-edge rank within dst (from hist)
__device__ __align__(16) int g_rank1[cE1];
__device__ int g_eidx0[cE0];
__device__ int g_eidx1[cE1];
__device__ int g_bsum[64];

// block counts
#define HB 1875          // hist/fill blocks: (cE0+cE1)/4/256
#define XB 25000         // x conv blocks: cN0*32/256
#define A0B 6250         // attr0 gather blocks
#define A1B 1250         // attr1 gather blocks
#define W0B 768
#define W1B 384
#define AGGB0 12500      // agg layer-0 blocks: cN1/4 (2 warps per node)
#define AGGB1 2500       // agg layer-1 blocks: cN2/4
#define ZB 59            // zero blocks: 15000 int4 / 256

// ---------------- PTX helpers ----------------
__device__ __forceinline__ uint32_t s2u(const void* p) {
    uint32_t a;
    asm("{ .reg .u64 t; cvta.to.shared.u64 t, %1; cvt.u32.u64 %0, t; }"
        : "=r"(a) : "l"(p));
    return a;
}

#define CP16(dst, src) \
    asm volatile("cp.async.cg.shared.global [%0], [%1], 16;" \
        :: "r"(dst), "l"(src) : "memory")
#define CP_COMMIT() asm volatile("cp.async.commit_group;" ::: "memory")
#define CP_WAIT(n) asm volatile("cp.async.wait_group %0;" :: "n"(n) : "memory")

#define LDM4(R, addr) \
    asm volatile("ldmatrix.sync.aligned.m8n8.x4.shared.b16 {%0,%1,%2,%3}, [%4];" \
        : "=r"((R)[0]), "=r"((R)[1]), "=r"((R)[2]), "=r"((R)[3]) : "r"(addr))

#define MMAH(d, a, b0, b1) \
    asm volatile("mma.sync.aligned.m16n8k16.row.col.f32.f16.f16.f32 " \
        "{%0,%1,%2,%3},{%4,%5,%6,%7},{%8,%9},{%0,%1,%2,%3};" \
        : "+f"((d)[0]), "+f"((d)[1]), "+f"((d)[2]), "+f"((d)[3]) \
        : "r"((a)[0]), "r"((a)[1]), "r"((a)[2]), "r"((a)[3]), \
          "r"(b0), "r"(b1))

__device__ __forceinline__ uint4 pack8(float4 a, float4 b) {
    __half2 h0 = __floats2half2_rn(a.x, a.y);
    __half2 h1 = __floats2half2_rn(a.z, a.w);
    __half2 h2 = __floats2half2_rn(b.x, b.y);
    __half2 h3 = __floats2half2_rn(b.z, b.w);
    uint4 r;
    r.x = *(uint32_t*)&h0; r.y = *(uint32_t*)&h1;
    r.z = *(uint32_t*)&h2; r.w = *(uint32_t*)&h3;
    return r;
}

// ---------------- k_front: hist+rank (atomics) ∪ x->fp16 (bandwidth) ---------
__global__ void k_front(const float* __restrict__ x, const int* __restrict__ dst0,
                        const int* __restrict__ dst1) {
    int b = blockIdx.x;
    if (b < HB) {  // histogram; atomic return value IS the edge's rank
        int i = b * 256 + threadIdx.x;
        if (i < cE0 / 4) {
            int4 d = ((const int4*)dst0)[i];
            int4 r;
            r.x = atomicAdd(&g_cnt0[d.x], 1);
            r.y = atomicAdd(&g_cnt0[d.y], 1);
            r.z = atomicAdd(&g_cnt0[d.z], 1);
            r.w = atomicAdd(&g_cnt0[d.w], 1);
            ((int4*)g_rank0)[i] = r;
        } else {
            int j = i - cE0 / 4;
            int4 d = ((const int4*)dst1)[j];
            int4 r;
            r.x = atomicAdd(&g_cnt1[d.x], 1);
            r.y = atomicAdd(&g_cnt1[d.y], 1);
            r.z = atomicAdd(&g_cnt1[d.z], 1);
            r.w = atomicAdd(&g_cnt1[d.w], 1);
            ((int4*)g_rank1)[j] = r;
        }
        return;
    }
    // x -> fp16, 8 floats/thread
    int i = (b - HB) * 256 + threadIdx.x;  // [0, cN0*32)
    const float4* p = (const float4*)x + (size_t)i * 2;
    ((uint4*)g_xh)[i] = pack8(p[0], p[1]);
}

// ---------------- psum: per-1024-chunk totals ----------------
__global__ void k_psum() {
    int b = blockIdx.x;
    int layer = (b >= NB0);
    const int* cnt = layer ? g_cnt1 : g_cnt0;
    int N = layer ? cN2 : cN1;
    int base = (layer ? (b - NB0) : b) * 1024;
    int t = threadIdx.x;
    int s = 0;
#pragma unroll
    for (int j = 0; j < 4; j++) {
        int i = base + t * 4 + j;
        if (i < N) s += cnt[i];
    }
    for (int o = 16; o; o >>= 1) s += __shfl_down_sync(0xFFFFFFFFu, s, o);
    __shared__ int ws[8];
    if ((t & 31) == 0) ws[t >> 5] = s;
    __syncthreads();
    if (t == 0) {
        int tot = 0;
        for (int w = 0; w < 8; w++) tot += ws[w];
        g_bsum[b] = tot;
    }
}

// ---------------- sfin: rowptr from counts ----------------
__global__ void k_sfin() {
    int b = blockIdx.x;
    int layer = (b >= NB0);
    const int* cnt = layer ? g_cnt1 : g_cnt0;
    int* rp = layer ? g_rp1 : g_rp0;
    int N = layer ? cN2 : cN1;
    int base = (layer ? (b - NB0) : b) * 1024;
    int t = threadIdx.x, lane = t & 31, w = t >> 5;

    __shared__ int sboff;
    if (t == 0) {
        int lo = layer ? NB0 : 0;
        int run = 0;
        for (int j = lo; j < b; j++) run += g_bsum[j];
        sboff = run;
        if (b == 0) {
            int tot = 0;
            for (int j = 0; j < NB0; j++) tot += g_bsum[j];
            g_rp0[cN1] = tot;
        }
        if (b == NB0) {
            int tot = 0;
            for (int j = NB0; j < NB0 + NB1; j++) tot += g_bsum[j];
            g_rp1[cN2] = tot;
        }
    }

    int i0 = base + t * 4;
    int v0 = (i0 + 0 < N) ? cnt[i0 + 0] : 0;
    int v1 = (i0 + 1 < N) ? cnt[i0 + 1] : 0;
    int v2 = (i0 + 2 < N) ? cnt[i0 + 2] : 0;
    int v3 = (i0 + 3 < N) ? cnt[i0 + 3] : 0;
    int tsum = v0 + v1 + v2 + v3;
    int sc = tsum;
    for (int o = 1; o < 32; o <<= 1) {
        int u = __shfl_up_sync(0xFFFFFFFFu, sc, o);
        if (lane >= o) sc += u;
    }
    __shared__ int wsum[8], woff[8];
    if (lane == 31) wsum[w] = sc;
    __syncthreads();
    if (t == 0) {
        int run = 0;
        for (int k = 0; k < 8; k++) { woff[k] = run; run += wsum[k]; }
    }
    __syncthreads();
    int ex = sc - tsum + woff[w] + sboff;
    if (i0 + 0 < N) rp[i0 + 0] = ex;
    if (i0 + 1 < N) rp[i0 + 1] = ex + v0;
    if (i0 + 2 < N) rp[i0 + 2] = ex + v0 + v1;
    if (i0 + 3 < N) rp[i0 + 3] = ex + v0 + v1 + v2;
}

// ---------------- k_mid: atomic-free CSR fill only ----------------
__global__ void k_mid(const int* __restrict__ src0, const int* __restrict__ dst0,
                      const int* __restrict__ src1, const int* __restrict__ dst1) {
    int i = blockIdx.x * 256 + threadIdx.x;
    if (i < cE0 / 4) {
        int4 s = ((const int4*)src0)[i];
        int4 d = ((const int4*)dst0)[i];
        int4 r = ((const int4*)g_rank0)[i];
        g_eidx0[g_rp0[d.x] + r.x] = s.x;
        g_eidx0[g_rp0[d.y] + r.y] = s.y;
        g_eidx0[g_rp0[d.z] + r.z] = s.z;
        g_eidx0[g_rp0[d.w] + r.w] = s.w;
    } else {
        int j = i - cE0 / 4;
        if (j < cE1 / 4) {
            int4 s = ((const int4*)src1)[j];
            int4 d = ((const int4*)dst1)[j];
            int4 r = ((const int4*)g_rank1)[j];
            g_eidx1[g_rp1[d.x] + r.x] = s.x;
            g_eidx1[g_rp1[d.y] + r.y] = s.y;
            g_eidx1[g_rp1[d.z] + r.z] = s.z;
            g_eidx1[g_rp1[d.w] + r.w] = s.w;
        }
    }
}

// ---------------- aggregation: 2 warps per node (uint2 lanes) ----------------
// layer 0 launch also carries: cnt re-zero, attr gathers, W/bias prep tails.
__global__ __launch_bounds__(256) void k_agg(
    int layer, const float* __restrict__ attr,
    const int* __restrict__ b0, const int* __restrict__ b1,
    const float* __restrict__ Wl0, const float* __restrict__ Wr0,
    const float* __restrict__ Wa0, const float* __restrict__ bl0,
    const float* __restrict__ ba0,
    const float* __restrict__ Wl1, const float* __restrict__ Wr1,
    const float* __restrict__ Wa1, const float* __restrict__ bl1,
    const float* __restrict__ ba1) {
    int blk = blockIdx.x;
    int aggN = layer ? AGGB1 : AGGB0;
    if (blk >= aggN) {  // layer-0 tail partitions only
        int b = blk - aggN;
        if (b < ZB) {  // re-zero cnt (entry invariant for next replay)
            int z = b * 256 + threadIdx.x;
            int4 zz = make_int4(0, 0, 0, 0);
            if (z < 12500) ((int4*)g_cnt0)[z] = zz;
            else if (z < 15000) ((int4*)g_cnt1)[z - 12500] = zz;
            return;
        }
        b -= ZB;
        if (b < A0B) {  // attr[batch0] -> fp16
            int i = b * 256 + threadIdx.x;
            int row = i >> 5, c = i & 31;
            const float4* p = (const float4*)(attr + (size_t)b0[row] * 256) + c * 2;
            ((uint4*)g_attr0h)[i] = pack8(p[0], p[1]);
            return;
        }
        b -= A0B;
        if (b < A1B) {  // attr[batch1] -> fp16
            int i = b * 256 + threadIdx.x;
            int row = i >> 5, c = i & 31;
            const float4* p = (const float4*)(attr + (size_t)b1[row] * 256) + c * 2;
            ((uint4*)g_attr1h)[i] = pack8(p[0], p[1]);
            return;
        }
        b -= A1B;
        if (b < W0B) {  // W0 transpose -> fp16
            int i = b * 256 + threadIdx.x;
            int k = i >> 8, n = i & 255;
            float v;
            if (k < 256) v = Wl0[k * 256 + n];
            else if (k < 512) v = Wr0[(k - 256) * 256 + n];
            else v = 0.25f * Wa0[(k - 512) * 256 + n];
            g_Wh0[n * 768 + k] = __float2half_rn(v);
            return;
        }
        b -= W0B;
        if (b < W1B) {  // W1 transpose -> fp16
            int i = b * 256 + threadIdx.x;
            int k = i >> 7, n = i & 127;
            float v;
            if (k < 256) v = Wl1[k * 128 + n];
            else if (k < 512) v = Wr1[(k - 256) * 128 + n];
            else v = 0.25f * Wa1[(k - 512) * 128 + n];
            g_Wh1[n * 768 + k] = __float2half_rn(v);
            return;
        }
        b -= W1B;
        {  // biases
            int i = b * 256 + threadIdx.x;
            if (i < 256) g_bias0[i] = bl0[i] + 0.25f * ba0[i];
            else if (i < 384) g_bias1[i - 256] = bl1[i - 256] + 0.25f * ba1[i - 256];
        }
        return;
    }

    const __half* X = layer ? g_hh : g_xh;
    const int* rp = layer ? g_rp1 : g_rp0;
    const int* eidx = layer ? g_eidx1 : g_eidx0;
    __half* mean = layer ? g_mean1h : g_mean0h;

    int node = blk * 4 + (threadIdx.x >> 6);      // 64 threads (2 warps) per node
    int half = (threadIdx.x >> 5) & 1;            // which 128-feature half
    int lane = threadIdx.x & 31;
    int b = rp[node], e = rp[node + 1];
    const uint2* X2 = (const uint2*)X;            // row = 64 uint2 (256 halves)
    int off = half * 32 + lane;                   // uint2 index within row

    float acc[4] = {0.f, 0.f, 0.f, 0.f};

    int p = b;
    for (; p + 4 <= e; p += 4) {
        int s0 = eidx[p], s1 = eidx[p + 1], s2 = eidx[p + 2], s3 = eidx[p + 3];
        uint2 v0 = X2[(size_t)s0 * 64 + off];
        uint2 v1 = X2[(size_t)s1 * 64 + off];
        uint2 v2 = X2[(size_t)s2 * 64 + off];
        uint2 v3 = X2[(size_t)s3 * 64 + off];
#pragma unroll
        for (int q = 0; q < 2; q++) {
            uint32_t w0 = (&v0.x)[q], w1 = (&v1.x)[q], w2 = (&v2.x)[q], w3 = (&v3.x)[q];
            float2 f0 = __half22float2(*(__half2*)&w0);
            float2 f1 = __half22float2(*(__half2*)&w1);
            float2 f2 = __half22float2(*(__half2*)&w2);
            float2 f3 = __half22float2(*(__half2*)&w3);
            acc[q * 2 + 0] += (f0.x + f1.x) + (f2.x + f3.x);
            acc[q * 2 + 1] += (f0.y + f1.y) + (f2.y + f3.y);
        }
    }
    for (; p < e; p++) {
        uint2 v = X2[(size_t)eidx[p] * 64 + off];
#pragma unroll
        for (int q = 0; q < 2; q++) {
            uint32_t w = (&v.x)[q];
            float2 f = __half22float2(*(__half2*)&w);
            acc[q * 2 + 0] += f.x;
            acc[q * 2 + 1] += f.y;
        }
    }
    float inv = 1.0f / (float)max(e - b, 1);
    uint2 o;
#pragma unroll
    for (int q = 0; q < 2; q++) {
        __half2 h = __floats2half2_rn(acc[q * 2] * inv, acc[q * 2 + 1] * inv);
        (&o.x)[q] = *(uint32_t*)&h;
    }
    ((uint2*)mean)[(size_t)node * 64 + off] = o;
}

// ---------------- fp16 mma.sync GEMM (CTA 128x128, BK=64, 3-stage) -----------
__global__ __launch_bounds__(256, 2) void k_gemm(int layer, float* __restrict__ outx,
                                                 int M, int N) {
    extern __shared__ char smc[];
    uint32_t sb = s2u(smc);

    const __half* sA0 = layer ? g_mean1h : g_mean0h;
    const __half* sA1 = layer ? g_hh : g_xh;
    const __half* sA2 = layer ? g_attr1h : g_attr0h;
    const __half* Wh = layer ? g_Wh1 : g_Wh0;
    const float* bias = layer ? g_bias1 : g_bias0;

    int tid = threadIdx.x, wid = tid >> 5, lane = tid & 31;
    int rowBlk = blockIdx.y * 128, colBlk = blockIdx.x * 128;

    auto issue = [&](int c) {
        const __half* Abase = (c < 4) ? sA0 : ((c < 8) ? sA1 : sA2);
        int klb = (c & 3) * 128;  // byte offset within 512B row
        uint32_t st = sb + (uint32_t)(c % 3) * 32768u;
#pragma unroll
        for (int i = 0; i < 4; i++) {
            int idx = i * 256 + tid;
            int row = idx >> 3, c4 = idx & 7;
            int gr = rowBlk + row;
            if (gr >= M) gr = M - 1;
            CP16(st + row * 128 + (((c4 ^ (row & 7)) << 4)),
                 (const char*)Abase + (size_t)gr * 512 + klb + c4 * 16);
            CP16(st + 16384 + row * 128 + (((c4 ^ (row & 7)) << 4)),
                 (const char*)Wh + (size_t)(colBlk + row) * 1536 + c * 128 + c4 * 16);
        }
        CP_COMMIT();
    };

    float acc[2][8][4];
#pragma unroll
    for (int mt = 0; mt < 2; mt++)
#pragma unroll
        for (int nt = 0; nt < 8; nt++)
#pragma unroll
            for (int q = 0; q < 4; q++) acc[mt][nt][q] = 0.f;

    issue(0);
    issue(1);

    int wm = (wid & 3) * 32, wn = (wid >> 2) * 64;

    for (int c = 0; c < 12; c++) {
        if (c >= 10) CP_WAIT(0); else CP_WAIT(1);
        __syncthreads();
        if (c + 2 < 12) issue(c + 2);
        uint32_t stA = sb + (uint32_t)(c % 3) * 32768u;
        uint32_t stB = stA + 16384u;
#pragma unroll
        for (int ks = 0; ks < 4; ks++) {
            uint32_t a[2][4], bf[4][4];
#pragma unroll
            for (int mt = 0; mt < 2; mt++) {
                int row = wm + mt * 16 + (lane & 15);
                int c4 = ks * 2 + (lane >> 4);
                LDM4(a[mt], stA + row * 128 + ((c4 ^ (row & 7)) << 4));
            }
#pragma unroll
            for (int bg = 0; bg < 4; bg++) {
                int n = wn + bg * 16 + (lane & 7) + ((lane >> 4) << 3);
                int c4 = ks * 2 + ((lane >> 3) & 1);
                LDM4(bf[bg], stB + n * 128 + ((c4 ^ (n & 7)) << 4));
            }
#pragma unroll
            for (int mt = 0; mt < 2; mt++)
#pragma unroll
                for (int bg = 0; bg < 4; bg++) {
                    MMAH(acc[mt][bg * 2 + 0], a[mt], bf[bg][0], bf[bg][1]);
                    MMAH(acc[mt][bg * 2 + 1], a[mt], bf[bg][2], bf[bg][3]);
                }
        }
    }

    // epilogue: bias + relu; layer0 -> g_hh (half), layer1 -> out (fp32)
    int r4 = lane >> 2, c2 = (lane & 3) * 2;
#pragma unroll
    for (int mt = 0; mt < 2; mt++) {
        int row0 = rowBlk + wm + mt * 16 + r4;
#pragma unroll
        for (int nt = 0; nt < 8; nt++) {
            int col = colBlk + wn + nt * 8 + c2;
            float b0 = bias[col], b1 = bias[col + 1];
            float v0 = fmaxf(acc[mt][nt][0] + b0, 0.f);
            float v1 = fmaxf(acc[mt][nt][1] + b1, 0.f);
            float v2 = fmaxf(acc[mt][nt][2] + b0, 0.f);
            float v3 = fmaxf(acc[mt][nt][3] + b1, 0.f);
            if (layer == 0) {
                __half2 h01 = __floats2half2_rn(v0, v1);
                __half2 h23 = __floats2half2_rn(v2, v3);
                if (row0 < M)
                    *(__half2*)(g_hh + (size_t)row0 * 256 + col) = h01;
                if (row0 + 8 < M)
                    *(__half2*)(g_hh + (size_t)(row0 + 8) * 256 + col) = h23;
            } else {
                if (row0 < M)
                    *(float2*)(outx + (size_t)row0 * N + col) = make_float2(v0, v1);
                if (row0 + 8 < M)
                    *(float2*)(outx + (size_t)(row0 + 8) * N + col) = make_float2(v2, v3);
            }
        }
    }
}

// ---------------- launch ----------------
extern "C" void kernel_launch(void* const* d_in, const int* in_sizes, int n_in,
                              void* d_out, int out_size) {
    const float* x = (const float*)d_in[0];
    const float* attr = (const float*)d_in[1];
    const int* src0 = (const int*)d_in[2];
    const int* dst0 = (const int*)d_in[3];
    const int* src1 = (const int*)d_in[4];
    const int* dst1 = (const int*)d_in[5];
    const int* batch0 = (const int*)d_in[6];
    const int* batch1 = (const int*)d_in[7];
    const float* W_l0 = (const float*)d_in[8];
    const float* b_l0 = (const float*)d_in[9];
    const float* W_r0 = (const float*)d_in[10];
    const float* W_l1 = (const float*)d_in[11];
    const float* b_l1 = (const float*)d_in[12];
    const float* W_r1 = (const float*)d_in[13];
    const float* W_a0 = (const float*)d_in[14];
    const float* b_a0 = (const float*)d_in[15];
    const float* W_a1 = (const float*)d_in[16];
    const float* b_a1 = (const float*)d_in[17];
    float* out = (float*)d_out;

    cudaFuncSetAttribute(k_gemm, cudaFuncAttributeMaxDynamicSharedMemorySize,
                         98304);

    k_front<<<HB + XB, 256>>>(x, dst0, dst1);
    k_psum<<<NB0 + NB1, 256>>>();
    k_sfin<<<NB0 + NB1, 256>>>();
    k_mid<<<HB, 256>>>(src0, dst0, src1, dst1);

    // agg layer 0 + tails (zero, attr0/attr1 gathers, W/bias prep)
    k_agg<<<AGGB0 + ZB + A0B + A1B + W0B + W1B + 2, 256>>>(
        0, attr, batch0, batch1,
        W_l0, W_r0, W_a0, b_l0, b_a0, W_l1, W_r1, W_a1, b_l1, b_a1);
    {
        dim3 grid(2, (cN1 + 127) / 128);
        k_gemm<<<grid, 256, 98304>>>(0, nullptr, cN1, 256);
    }
    k_agg<<<AGGB1, 256>>>(1, attr, batch0, batch1,
                          W_l0, W_r0, W_a0, b_l0, b_a0,
                          W_l1, W_r1, W_a1, b_l1, b_a1);
    {
        dim3 grid(1, (cN2 + 127) / 128);
        k_gemm<<<grid, 256, 98304>>>(1, out, cN2, 128);
    }
}

// round 17
// speedup vs baseline: 1.0467x; 1.0467x over previous
#include <cuda_runtime.h>
#include <cuda_fp16.h>
#include <cstdint>

#define cN0 200000
#define cN1 50000
#define cN2 10000
#define cE0 1600000
#define cE1 320000
#define NB0 49
#define NB1 10

// ---------------- device scratch ----------------
__device__ __align__(128) __half g_xh[cN0 * 256];      // all x, fp16
__device__ __align__(128) __half g_hh[cN1 * 256];      // h (layer-0 out), fp16
__device__ __align__(128) __half g_mean0h[cN1 * 256];
__device__ __align__(128) __half g_mean1h[cN2 * 256];
__device__ __align__(128) __half g_attr0h[cN1 * 256];  // attr[batch0]
__device__ __align__(128) __half g_attr1h[cN2 * 256];  // attr[batch1]
__device__ __align__(128) __half g_Wh0[256 * 768];     // [n][k]
__device__ __align__(128) __half g_Wh1[128 * 768];
__device__ float g_bias0[256];
__device__ float g_bias1[128];
// zero at module load; re-zeroed by agg0 tail blocks each run (entry invariant)
__device__ __align__(16) int g_cnt0[cN1];
__device__ __align__(16) int g_cnt1[cN2];
__device__ int g_rp0[cN1 + 1];
__device__ int g_rp1[cN2 + 1];
__device__ __align__(16) int g_rank0[cE0];  // per-edge rank within dst (from hist)
__device__ __align__(16) int g_rank1[cE1];
__device__ int g_eidx0[cE0];
__device__ int g_eidx1[cE1];
__device__ int g_bsum[64];

// block counts
#define HB 1875          // hist/fill blocks: (cE0+cE1)/4/256
#define XB 25000         // x conv blocks: cN0*32/256
#define A0B 6250         // attr0 gather blocks
#define A1B 1250         // attr1 gather blocks
#define W0B 768
#define W1B 384
#define AGG0B 6250       // agg layer-0 blocks: cN1/8 (1 warp per node)
#define ZB 59            // zero blocks: 15000 int4 / 256

// ---------------- PTX helpers ----------------
__device__ __forceinline__ uint32_t s2u(const void* p) {
    uint32_t a;
    asm("{ .reg .u64 t; cvta.to.shared.u64 t, %1; cvt.u32.u64 %0, t; }"
        : "=r"(a) : "l"(p));
    return a;
}

#define CP16(dst, src) \
    asm volatile("cp.async.cg.shared.global [%0], [%1], 16;" \
        :: "r"(dst), "l"(src) : "memory")
#define CP_COMMIT() asm volatile("cp.async.commit_group;" ::: "memory")
#define CP_WAIT(n) asm volatile("cp.async.wait_group %0;" :: "n"(n) : "memory")

#define LDM4(R, addr) \
    asm volatile("ldmatrix.sync.aligned.m8n8.x4.shared.b16 {%0,%1,%2,%3}, [%4];" \
        : "=r"((R)[0]), "=r"((R)[1]), "=r"((R)[2]), "=r"((R)[3]) : "r"(addr))

#define MMAH(d, a, b0, b1) \
    asm volatile("mma.sync.aligned.m16n8k16.row.col.f32.f16.f16.f32 " \
        "{%0,%1,%2,%3},{%4,%5,%6,%7},{%8,%9},{%0,%1,%2,%3};" \
        : "+f"((d)[0]), "+f"((d)[1]), "+f"((d)[2]), "+f"((d)[3]) \
        : "r"((a)[0]), "r"((a)[1]), "r"((a)[2]), "r"((a)[3]), \
          "r"(b0), "r"(b1))

__device__ __forceinline__ uint4 pack8(float4 a, float4 b) {
    __half2 h0 = __floats2half2_rn(a.x, a.y);
    __half2 h1 = __floats2half2_rn(a.z, a.w);
    __half2 h2 = __floats2half2_rn(b.x, b.y);
    __half2 h3 = __floats2half2_rn(b.z, b.w);
    uint4 r;
    r.x = *(uint32_t*)&h0; r.y = *(uint32_t*)&h1;
    r.z = *(uint32_t*)&h2; r.w = *(uint32_t*)&h3;
    return r;
}

// ---------------- k_pre: hist+rank (atomics) ∪ attr gathers ∪ W/bias prep ----
// Contains everything psum/sfin depend on (hist) plus independent prep work
// that hides inside the hist's atomic latency.
__global__ void k_pre(const int* __restrict__ dst0, const int* __restrict__ dst1,
                      const float* __restrict__ attr,
                      const int* __restrict__ b0, const int* __restrict__ b1,
                      const float* __restrict__ Wl0, const float* __restrict__ Wr0,
                      const float* __restrict__ Wa0, const float* __restrict__ bl0,
                      const float* __restrict__ ba0,
                      const float* __restrict__ Wl1, const float* __restrict__ Wr1,
                      const float* __restrict__ Wa1, const float* __restrict__ bl1,
                      const float* __restrict__ ba1) {
    int b = blockIdx.x;
    if (b < HB) {  // histogram; atomic return value IS the edge's rank
        int i = b * 256 + threadIdx.x;
        if (i < cE0 / 4) {
            int4 d = ((const int4*)dst0)[i];
            int4 r;
            r.x = atomicAdd(&g_cnt0[d.x], 1);
            r.y = atomicAdd(&g_cnt0[d.y], 1);
            r.z = atomicAdd(&g_cnt0[d.z], 1);
            r.w = atomicAdd(&g_cnt0[d.w], 1);
            ((int4*)g_rank0)[i] = r;
        } else {
            int j = i - cE0 / 4;
            int4 d = ((const int4*)dst1)[j];
            int4 r;
            r.x = atomicAdd(&g_cnt1[d.x], 1);
            r.y = atomicAdd(&g_cnt1[d.y], 1);
            r.z = atomicAdd(&g_cnt1[d.z], 1);
            r.w = atomicAdd(&g_cnt1[d.w], 1);
            ((int4*)g_rank1)[j] = r;
        }
        return;
    }
    b -= HB;
    if (b < A0B) {  // attr[batch0] -> fp16
        int i = b * 256 + threadIdx.x;  // [0, cN1*32)
        int row = i >> 5, c = i & 31;
        const float4* p = (const float4*)(attr + (size_t)b0[row] * 256) + c * 2;
        ((uint4*)g_attr0h)[i] = pack8(p[0], p[1]);
        return;
    }
    b -= A0B;
    if (b < A1B) {  // attr[batch1] -> fp16
        int i = b * 256 + threadIdx.x;  // [0, cN2*32)
        int row = i >> 5, c = i & 31;
        const float4* p = (const float4*)(attr + (size_t)b1[row] * 256) + c * 2;
        ((uint4*)g_attr1h)[i] = pack8(p[0], p[1]);
        return;
    }
    b -= A1B;
    if (b < W0B) {  // W0 transpose -> fp16
        int i = b * 256 + threadIdx.x;  // [0, 768*256)
        int k = i >> 8, n = i & 255;
        float v;
        if (k < 256) v = Wl0[k * 256 + n];
        else if (k < 512) v = Wr0[(k - 256) * 256 + n];
        else v = 0.25f * Wa0[(k - 512) * 256 + n];
        g_Wh0[n * 768 + k] = __float2half_rn(v);
        return;
    }
    b -= W0B;
    if (b < W1B) {  // W1 transpose -> fp16
        int i = b * 256 + threadIdx.x;  // [0, 768*128)
        int k = i >> 7, n = i & 127;
        float v;
        if (k < 256) v = Wl1[k * 128 + n];
        else if (k < 512) v = Wr1[(k - 256) * 128 + n];
        else v = 0.25f * Wa1[(k - 512) * 128 + n];
        g_Wh1[n * 768 + k] = __float2half_rn(v);
        return;
    }
    b -= W1B;
    {  // biases (2 blocks = 512 threads; need 384)
        int i = b * 256 + threadIdx.x;
        if (i < 256) g_bias0[i] = bl0[i] + 0.25f * ba0[i];
        else if (i < 384) g_bias1[i - 256] = bl1[i - 256] + 0.25f * ba1[i - 256];
    }
}

// ---------------- psum: per-1024-chunk totals ----------------
__global__ void k_psum() {
    int b = blockIdx.x;
    int layer = (b >= NB0);
    const int* cnt = layer ? g_cnt1 : g_cnt0;
    int N = layer ? cN2 : cN1;
    int base = (layer ? (b - NB0) : b) * 1024;
    int t = threadIdx.x;
    int s = 0;
#pragma unroll
    for (int j = 0; j < 4; j++) {
        int i = base + t * 4 + j;
        if (i < N) s += cnt[i];
    }
    for (int o = 16; o; o >>= 1) s += __shfl_down_sync(0xFFFFFFFFu, s, o);
    __shared__ int ws[8];
    if ((t & 31) == 0) ws[t >> 5] = s;
    __syncthreads();
    if (t == 0) {
        int tot = 0;
        for (int w = 0; w < 8; w++) tot += ws[w];
        g_bsum[b] = tot;
    }
}

// ---------------- sfin: rowptr from counts ----------------
__global__ void k_sfin() {
    int b = blockIdx.x;
    int layer = (b >= NB0);
    const int* cnt = layer ? g_cnt1 : g_cnt0;
    int* rp = layer ? g_rp1 : g_rp0;
    int N = layer ? cN2 : cN1;
    int base = (layer ? (b - NB0) : b) * 1024;
    int t = threadIdx.x, lane = t & 31, w = t >> 5;

    __shared__ int sboff;
    if (t == 0) {
        int lo = layer ? NB0 : 0;
        int run = 0;
        for (int j = lo; j < b; j++) run += g_bsum[j];
        sboff = run;
        if (b == 0) {
            int tot = 0;
            for (int j = 0; j < NB0; j++) tot += g_bsum[j];
            g_rp0[cN1] = tot;
        }
        if (b == NB0) {
            int tot = 0;
            for (int j = NB0; j < NB0 + NB1; j++) tot += g_bsum[j];
            g_rp1[cN2] = tot;
        }
    }

    int i0 = base + t * 4;
    int v0 = (i0 + 0 < N) ? cnt[i0 + 0] : 0;
    int v1 = (i0 + 1 < N) ? cnt[i0 + 1] : 0;
    int v2 = (i0 + 2 < N) ? cnt[i0 + 2] : 0;
    int v3 = (i0 + 3 < N) ? cnt[i0 + 3] : 0;
    int tsum = v0 + v1 + v2 + v3;
    int sc = tsum;
    for (int o = 1; o < 32; o <<= 1) {
        int u = __shfl_up_sync(0xFFFFFFFFu, sc, o);
        if (lane >= o) sc += u;
    }
    __shared__ int wsum[8], woff[8];
    if (lane == 31) wsum[w] = sc;
    __syncthreads();
    if (t == 0) {
        int run = 0;
        for (int k = 0; k < 8; k++) { woff[k] = run; run += wsum[k]; }
    }
    __syncthreads();
    int ex = sc - tsum + woff[w] + sboff;
    if (i0 + 0 < N) rp[i0 + 0] = ex;
    if (i0 + 1 < N) rp[i0 + 1] = ex + v0;
    if (i0 + 2 < N) rp[i0 + 2] = ex + v0 + v1;
    if (i0 + 3 < N) rp[i0 + 3] = ex + v0 + v1 + v2;
}

// ---------------- k_mid: atomic-free fill ∪ x->fp16 conversion ---------------
// fill's scatter latency hides under the 307 MB conversion stream.
__global__ void k_mid(const int* __restrict__ src0, const int* __restrict__ dst0,
                      const int* __restrict__ src1, const int* __restrict__ dst1,
                      const float* __restrict__ x) {
    int b = blockIdx.x;
    if (b < HB) {  // CSR fill, no atomics: scatter position = rp[dst] + rank
        int i = b * 256 + threadIdx.x;
        if (i < cE0 / 4) {
            int4 s = ((const int4*)src0)[i];
            int4 d = ((const int4*)dst0)[i];
            int4 r = ((const int4*)g_rank0)[i];
            g_eidx0[g_rp0[d.x] + r.x] = s.x;
            g_eidx0[g_rp0[d.y] + r.y] = s.y;
            g_eidx0[g_rp0[d.z] + r.z] = s.z;
            g_eidx0[g_rp0[d.w] + r.w] = s.w;
        } else {
            int j = i - cE0 / 4;
            int4 s = ((const int4*)src1)[j];
            int4 d = ((const int4*)dst1)[j];
            int4 r = ((const int4*)g_rank1)[j];
            g_eidx1[g_rp1[d.x] + r.x] = s.x;
            g_eidx1[g_rp1[d.y] + r.y] = s.y;
            g_eidx1[g_rp1[d.z] + r.z] = s.z;
            g_eidx1[g_rp1[d.w] + r.w] = s.w;
        }
        return;
    }
    // x -> fp16, 8 floats/thread
    int i = (b - HB) * 256 + threadIdx.x;  // [0, cN0*32)
    const float4* p = (const float4*)x + (size_t)i * 2;
    ((uint4*)g_xh)[i] = pack8(p[0], p[1]);
}

// ---------------- mean aggregation: one warp per node (MLP=4, proven) --------
__global__ __launch_bounds__(256) void k_agg(int layer) {
    if (layer == 0 && blockIdx.x >= AGG0B) {
        // re-establish cnt = 0 entry invariant for the next graph replay
        int z = (blockIdx.x - AGG0B) * 256 + threadIdx.x;
        int4 zz = make_int4(0, 0, 0, 0);
        if (z < 12500) ((int4*)g_cnt0)[z] = zz;
        else if (z < 15000) ((int4*)g_cnt1)[z - 12500] = zz;
        return;
    }
    const __half* X = layer ? g_hh : g_xh;
    const int* rp = layer ? g_rp1 : g_rp0;
    const int* eidx = layer ? g_eidx1 : g_eidx0;
    __half* mean = layer ? g_mean1h : g_mean0h;
    int N = layer ? cN2 : cN1;

    int node = blockIdx.x * 8 + (threadIdx.x >> 5);
    if (node >= N) return;
    int lane = threadIdx.x & 31;
    int b = rp[node], e = rp[node + 1];
    const uint4* X4 = (const uint4*)X;  // row = 32 uint4 (256 halves)

    float acc[8];
#pragma unroll
    for (int q = 0; q < 8; q++) acc[q] = 0.f;

    int p = b;
    for (; p + 4 <= e; p += 4) {
        int s0 = eidx[p], s1 = eidx[p + 1], s2 = eidx[p + 2], s3 = eidx[p + 3];
        uint4 v0 = X4[(size_t)s0 * 32 + lane];
        uint4 v1 = X4[(size_t)s1 * 32 + lane];
        uint4 v2 = X4[(size_t)s2 * 32 + lane];
        uint4 v3 = X4[(size_t)s3 * 32 + lane];
#pragma unroll
        for (int q = 0; q < 4; q++) {
            uint32_t w0 = (&v0.x)[q], w1 = (&v1.x)[q], w2 = (&v2.x)[q], w3 = (&v3.x)[q];
            float2 f0 = __half22float2(*(__half2*)&w0);
            float2 f1 = __half22float2(*(__half2*)&w1);
            float2 f2 = __half22float2(*(__half2*)&w2);
            float2 f3 = __half22float2(*(__half2*)&w3);
            acc[q * 2 + 0] += (f0.x + f1.x) + (f2.x + f3.x);
            acc[q * 2 + 1] += (f0.y + f1.y) + (f2.y + f3.y);
        }
    }
    for (; p < e; p++) {
        uint4 v = X4[(size_t)eidx[p] * 32 + lane];
#pragma unroll
        for (int q = 0; q < 4; q++) {
            uint32_t w = (&v.x)[q];
            float2 f = __half22float2(*(__half2*)&w);
            acc[q * 2 + 0] += f.x;
            acc[q * 2 + 1] += f.y;
        }
    }
    float inv = 1.0f / (float)max(e - b, 1);
    uint4 o;
#pragma unroll
    for (int q = 0; q < 4; q++) {
        __half2 h = __floats2half2_rn(acc[q * 2] * inv, acc[q * 2 + 1] * inv);
        (&o.x)[q] = *(uint32_t*)&h;
    }
    ((uint4*)mean)[(size_t)node * 32 + lane] = o;
}

// ---------------- fp16 mma.sync GEMM (CTA 128x128, BK=64, 3-stage) -----------
__global__ __launch_bounds__(256, 2) void k_gemm(int layer, float* __restrict__ outx,
                                                 int M, int N) {
    extern __shared__ char smc[];
    uint32_t sb = s2u(smc);

    const __half* sA0 = layer ? g_mean1h : g_mean0h;
    const __half* sA1 = layer ? g_hh : g_xh;
    const __half* sA2 = layer ? g_attr1h : g_attr0h;
    const __half* Wh = layer ? g_Wh1 : g_Wh0;
    const float* bias = layer ? g_bias1 : g_bias0;

    int tid = threadIdx.x, wid = tid >> 5, lane = tid & 31;
    int rowBlk = blockIdx.y * 128, colBlk = blockIdx.x * 128;

    auto issue = [&](int c) {
        const __half* Abase = (c < 4) ? sA0 : ((c < 8) ? sA1 : sA2);
        int klb = (c & 3) * 128;  // byte offset within 512B row
        uint32_t st = sb + (uint32_t)(c % 3) * 32768u;
#pragma unroll
        for (int i = 0; i < 4; i++) {
            int idx = i * 256 + tid;
            int row = idx >> 3, c4 = idx & 7;
            int gr = rowBlk + row;
            if (gr >= M) gr = M - 1;
            CP16(st + row * 128 + (((c4 ^ (row & 7)) << 4)),
                 (const char*)Abase + (size_t)gr * 512 + klb + c4 * 16);
            CP16(st + 16384 + row * 128 + (((c4 ^ (row & 7)) << 4)),
                 (const char*)Wh + (size_t)(colBlk + row) * 1536 + c * 128 + c4 * 16);
        }
        CP_COMMIT();
    };

    float acc[2][8][4];
#pragma unroll
    for (int mt = 0; mt < 2; mt++)
#pragma unroll
        for (int nt = 0; nt < 8; nt++)
#pragma unroll
            for (int q = 0; q < 4; q++) acc[mt][nt][q] = 0.f;

    issue(0);
    issue(1);

    int wm = (wid & 3) * 32, wn = (wid >> 2) * 64;

    for (int c = 0; c < 12; c++) {
        if (c >= 10) CP_WAIT(0); else CP_WAIT(1);
        __syncthreads();
        if (c + 2 < 12) issue(c + 2);
        uint32_t stA = sb + (uint32_t)(c % 3) * 32768u;
        uint32_t stB = stA + 16384u;
#pragma unroll
        for (int ks = 0; ks < 4; ks++) {
            uint32_t a[2][4], bf[4][4];
#pragma unroll
            for (int mt = 0; mt < 2; mt++) {
                int row = wm + mt * 16 + (lane & 15);
                int c4 = ks * 2 + (lane >> 4);
                LDM4(a[mt], stA + row * 128 + ((c4 ^ (row & 7)) << 4));
            }
#pragma unroll
            for (int bg = 0; bg < 4; bg++) {
                int n = wn + bg * 16 + (lane & 7) + ((lane >> 4) << 3);
                int c4 = ks * 2 + ((lane >> 3) & 1);
                LDM4(bf[bg], stB + n * 128 + ((c4 ^ (n & 7)) << 4));
            }
#pragma unroll
            for (int mt = 0; mt < 2; mt++)
#pragma unroll
                for (int bg = 0; bg < 4; bg++) {
                    MMAH(acc[mt][bg * 2 + 0], a[mt], bf[bg][0], bf[bg][1]);
                    MMAH(acc[mt][bg * 2 + 1], a[mt], bf[bg][2], bf[bg][3]);
                }
        }
    }

    // epilogue: bias + relu; layer0 -> g_hh (half), layer1 -> out (fp32)
    int r4 = lane >> 2, c2 = (lane & 3) * 2;
#pragma unroll
    for (int mt = 0; mt < 2; mt++) {
        int row0 = rowBlk + wm + mt * 16 + r4;
#pragma unroll
        for (int nt = 0; nt < 8; nt++) {
            int col = colBlk + wn + nt * 8 + c2;
            float b0 = bias[col], b1 = bias[col + 1];
            float v0 = fmaxf(acc[mt][nt][0] + b0, 0.f);
            float v1 = fmaxf(acc[mt][nt][1] + b1, 0.f);
            float v2 = fmaxf(acc[mt][nt][2] + b0, 0.f);
            float v3 = fmaxf(acc[mt][nt][3] + b1, 0.f);
            if (layer == 0) {
                __half2 h01 = __floats2half2_rn(v0, v1);
                __half2 h23 = __floats2half2_rn(v2, v3);
                if (row0 < M)
                    *(__half2*)(g_hh + (size_t)row0 * 256 + col) = h01;
                if (row0 + 8 < M)
                    *(__half2*)(g_hh + (size_t)(row0 + 8) * 256 + col) = h23;
            } else {
                if (row0 < M)
                    *(float2*)(outx + (size_t)row0 * N + col) = make_float2(v0, v1);
                if (row0 + 8 < M)
                    *(float2*)(outx + (size_t)(row0 + 8) * N + col) = make_float2(v2, v3);
            }
        }
    }
}

// ---------------- launch ----------------
extern "C" void kernel_launch(void* const* d_in, const int* in_sizes, int n_in,
                              void* d_out, int out_size) {
    const float* x = (const float*)d_in[0];
    const float* attr = (const float*)d_in[1];
    const int* src0 = (const int*)d_in[2];
    const int* dst0 = (const int*)d_in[3];
    const int* src1 = (const int*)d_in[4];
    const int* dst1 = (const int*)d_in[5];
    const int* batch0 = (const int*)d_in[6];
    const int* batch1 = (const int*)d_in[7];
    const float* W_l0 = (const float*)d_in[8];
    const float* b_l0 = (const float*)d_in[9];
    const float* W_r0 = (const float*)d_in[10];
    const float* W_l1 = (const float*)d_in[11];
    const float* b_l1 = (const float*)d_in[12];
    const float* W_r1 = (const float*)d_in[13];
    const float* W_a0 = (const float*)d_in[14];
    const float* b_a0 = (const float*)d_in[15];
    const float* W_a1 = (const float*)d_in[16];
    const float* b_a1 = (const float*)d_in[17];
    float* out = (float*)d_out;

    cudaFuncSetAttribute(k_gemm, cudaFuncAttributeMaxDynamicSharedMemorySize,
                         98304);

    // front chain: psum/sfin only wait on the small hist kernel now
    k_pre<<<HB + A0B + A1B + W0B + W1B + 2, 256>>>(
        dst0, dst1, attr, batch0, batch1,
        W_l0, W_r0, W_a0, b_l0, b_a0, W_l1, W_r1, W_a1, b_l1, b_a1);
    k_psum<<<NB0 + NB1, 256>>>();
    k_sfin<<<NB0 + NB1, 256>>>();
    k_mid<<<HB + XB, 256>>>(src0, dst0, src1, dst1, x);

    k_agg<<<AGG0B + ZB, 256>>>(0);
    {
        dim3 grid(2, (cN1 + 127) / 128);
        k_gemm<<<grid, 256, 98304>>>(0, nullptr, cN1, 256);
    }
    k_agg<<<(cN2 + 7) / 8, 256>>>(1);
    {
        dim3 grid(1, (cN2 + 127) / 128);
        k_gemm<<<grid, 256, 98304>>>(1, out, cN2, 128);
    }
}